// round 5
// baseline (speedup 1.0000x reference)
#include <cuda_runtime.h>
#include <stdint.h>
#include <math.h>

#define NPOS 256          // positions per block
#define THREADS 128       // 2 positions per thread
#define CH 84
#define L_SEQ 8192
#define B_SEQ 16

// smem layout (float offsets)
#define AB_OFF 0          // 64 dims * 16 states * 2 (A,B) = 2048
#define SB_OFF 2048       // class emit [s][q] 16*16       = 256
#define K_OFF  2304       // 16
#define SCR_OFF 2320      // 240 prep scratch
#define NB_OFF 2560       // 260 float4 nuc halo           = 1040
#define C0_OFF 3600       // 256 * 20 (ch 0..15 + pad)     = 5120
#define E_OFF  8720       // 256 * 36 (32-ch chunk + pad)  = 9216
#define SMEM_FLOATS 17936
#define SMEM_BYTES (SMEM_FLOATS * 4)   // 71744 B -> 3 blocks/SM

#define C0S 20
#define ES  36

typedef unsigned long long ull;

__device__ __forceinline__ ull fma2(ull a, ull b, ull c) {
    ull d;
    asm("fma.rn.f32x2 %0, %1, %2, %3;" : "=l"(d) : "l"(a), "l"(b), "l"(c));
    return d;
}
__device__ __forceinline__ ull pk2(float lo, float hi) {
    ull d;
    asm("mov.b64 %0, {%1, %2};" : "=l"(d) : "f"(lo), "f"(hi));
    return d;
}
__device__ __forceinline__ void upk2(float& lo, float& hi, ull v) {
    asm("mov.b64 {%0, %1}, %2;" : "=f"(lo), "=f"(hi) : "l"(v));
}
__device__ __forceinline__ void cp_async16(unsigned int saddr, const void* gaddr) {
    asm volatile("cp.async.cg.shared.global [%0], [%1], 16;" :: "r"(saddr), "l"(gaddr));
}

__device__ __forceinline__ void codon_full(const float4* nbp, float* fullv) {
    float4 m2 = nbp[0], m1 = nbp[1], c0 = nbp[2], q1 = nbp[3], q2 = nbp[4];
    float S_c0 = c0.x + c0.y + c0.z + c0.w;
    float S_q1 = q1.x + q1.y + q1.z + q1.w;
    float S_q2 = q2.x + q2.y + q2.z + q2.w;
    float S_m1 = m1.x + m1.y + m1.z + m1.w;
    float S_m2 = m2.x + m2.y + m2.z + m2.w;
    float L_any   = S_c0 * S_q1 * S_q2 * (1.f / 64.f);
    float L_start = c0.x * q1.w * q2.z;           // ATG
    float L_ib    = 0.25f * S_c0 * q1.z * q2.w;   // NGT
    float Pall = S_m2 * S_m1 * S_c0;
    float tAA = m1.x * c0.x, tAG = m1.x * c0.z, tGA = m1.z * c0.x;
    float R_ns   = (Pall - m2.w * (tAA + tAG + tGA)) * (1.f / 61.f);
    float R_any  = Pall * (1.f / 64.f);
    float R_iep  = m2.x * m1.z * 0.25f * S_c0;    // AGN
    float R_stop = m2.w * (0.34f * tAA + 0.33f * tAG + 0.33f * tGA);
    fullv[0] = 1.f; fullv[1] = 1.f; fullv[2] = 1.f;
    fullv[3] = 1.f; fullv[4] = 1.f; fullv[5] = 1.f;
    fullv[6]  = L_any * R_ns;
    fullv[7]  = L_start * R_any;
    fullv[8]  = L_ib * R_any;
    fullv[9]  = L_ib * R_ns;
    fullv[10] = L_ib * R_any;
    fullv[11] = L_any * R_iep;
    fullv[12] = L_any * R_iep;
    fullv[13] = L_any * R_iep;
    fullv[14] = L_any * R_stop;
}

__global__ void __launch_bounds__(THREADS, 3)
emit_kernel(const float* __restrict__ inputs,
            const float* __restrict__ eh,
            const float* __restrict__ ek,
            const float* __restrict__ eek,
            float* __restrict__ out) {
    extern __shared__ float sm[];
    const int tid = threadIdx.x;
    const int b  = blockIdx.x >> 5;
    const int p0 = (blockIdx.x & 31) << 8;
    const float* gbase = inputs + (size_t)(b * L_SEQ + p0) * CH;

    // ---- phase 0: async chunk loads ----
    unsigned int c0base = (unsigned int)__cvta_generic_to_shared(sm + C0_OFF);
    unsigned int ebase  = (unsigned int)__cvta_generic_to_shared(sm + E_OFF);
    // C0: channels 0..15, 4 float4 per position
#pragma unroll 2
    for (int i = tid; i < NPOS * 4; i += THREADS) {
        int pos = i >> 2, j = i & 3;
        cp_async16(c0base + (pos * C0S + j * 4) * 4, gbase + pos * CH + j * 4);
    }
    asm volatile("cp.async.commit_group;");
    // E1: channels 16..47, 8 float4 per position
#pragma unroll 2
    for (int i = tid; i < NPOS * 8; i += THREADS) {
        int pos = i >> 3, j = i & 7;
        cp_async16(ebase + (pos * ES + j * 4) * 4, gbase + pos * CH + 16 + j * 4);
    }
    asm volatile("cp.async.commit_group;");

    // ---- inline prep ----
    const float kscale = (float)(1.4426950408889634 / 100.0); // log2(e)/TEMP
    const float basec  = (float)log(expm1(sqrt(0.05)));
    const float cconst = (float)(0.5 * 64.0 * log(2.0 * M_PI));

    if (tid < 15) {               // softmax rows -> SB[s][q]
        int q = tid;
        float m = -1e30f;
        for (int s = 0; s < 15; s++) m = fmaxf(m, ek[q * 15 + s]);
        float e[15]; float sum = 0.f;
        for (int s = 0; s < 15; s++) { e[s] = expf(ek[q * 15 + s] - m); sum += e[s]; }
        float inv = 1.f / sum;
        for (int s = 0; s < 15; s++) sm[SB_OFF + s * 16 + q] = e[s] * inv;
    }
    if (tid == 15) {
        for (int s = 0; s < 16; s++) sm[SB_OFF + s * 16 + 15] = 0.f;
    }
    if (tid < 120) {              // MVN coefficients
        int s = tid >> 3, g = tid & 7;
        float Cp = 0.f, ldp = 0.f;
        for (int k = 0; k < 8; k++) {
            int d = g * 8 + k;
            float mu = eek[s * 128 + d];
            float v  = eek[s * 128 + 64 + d] + basec;
            float sp = (v > 20.f) ? v : log1pf(expf(v));
            float is2 = 1.f / (sp * sp);
            sm[AB_OFF + d * 32 + s * 2 + 0] = -0.5f * is2 * kscale;
            sm[AB_OFF + d * 32 + s * 2 + 1] = mu * is2 * kscale;
            Cp  = fmaf(mu * mu, is2, Cp);
            ldp += logf(sp);
        }
        sm[SCR_OFF + tid * 2 + 0] = Cp;
        sm[SCR_OFF + tid * 2 + 1] = ldp;
    } else if (tid >= 120 && tid < 128) {
        int g = tid - 120;        // zero-pad state 15
        for (int k = 0; k < 8; k++) {
            int d = g * 8 + k;
            sm[AB_OFF + d * 32 + 30] = 0.f;
            sm[AB_OFF + d * 32 + 31] = 0.f;
        }
    }

    // ---- nuc halo from global ----
    float4* nb = (float4*)(sm + NB_OFF);
#pragma unroll 2
    for (int i = tid; i < NPOS + 4; i += THREADS) {
        int gl = p0 + i - 2;
        float4 nv;
        if (gl >= 0 && gl < L_SEQ) {
            const float* nr = inputs + (size_t)(b * L_SEQ + gl) * CH;
            float n0 = nr[79];
            float4 f = *(const float4*)(nr + 80);   // ch 80..83
            nv = make_float4(fmaf(0.25f, f.w, n0),  fmaf(0.25f, f.w, f.x),
                             fmaf(0.25f, f.w, f.y), fmaf(0.25f, f.w, f.z));
        } else {
            nv = make_float4(0.25f, 0.25f, 0.25f, 0.25f);
        }
        nb[i] = nv;
    }
    __syncthreads();
    if (tid < 15) {
        float C = 0.f, ld = 0.f;
        for (int g = 0; g < 8; g++) {
            C  += sm[SCR_OFF + (tid * 8 + g) * 2 + 0];
            ld += sm[SCR_OFF + (tid * 8 + g) * 2 + 1];
        }
        sm[K_OFF + tid] = (-0.5f * C - ld - cconst) * kscale;
    } else if (tid == 15) {
        sm[K_OFF + 15] = 0.f;
    }
    asm volatile("cp.async.wait_group 1;");  // C0 ready
    __syncthreads();

    float* row0 = sm + C0_OFF + tid * C0S;
    float* row1 = row0 + 128 * C0S;

    // ====== phase A: class matvec + codon + hints -> staged into C0 rows ======
    {
        float cls0[16], cls1[16];
#pragma unroll
        for (int j = 0; j < 4; j++) {
            *(float4*)(cls0 + 4 * j) = *(const float4*)(row0 + 4 * j);
            *(float4*)(cls1 + 4 * j) = *(const float4*)(row1 + 4 * j);
        }
        ull c0a[8], c1a[8];
#pragma unroll
        for (int h = 0; h < 8; h++) { c0a[h] = 0; c1a[h] = 0; }
#pragma unroll 3
        for (int s = 0; s < 15; s++) {
            const ulonglong2* br = (const ulonglong2*)(sm + SB_OFF + s * 16);
            ulonglong2 b01 = br[0], b23 = br[1], b45 = br[2], b67 = br[3];
            ull p0r = pk2(cls0[s], cls0[s]);
            ull p1r = pk2(cls1[s], cls1[s]);
            c0a[0]=fma2(b01.x,p0r,c0a[0]); c0a[1]=fma2(b01.y,p0r,c0a[1]);
            c0a[2]=fma2(b23.x,p0r,c0a[2]); c0a[3]=fma2(b23.y,p0r,c0a[3]);
            c0a[4]=fma2(b45.x,p0r,c0a[4]); c0a[5]=fma2(b45.y,p0r,c0a[5]);
            c0a[6]=fma2(b67.x,p0r,c0a[6]); c0a[7]=fma2(b67.y,p0r,c0a[7]);
            c1a[0]=fma2(b01.x,p1r,c1a[0]); c1a[1]=fma2(b01.y,p1r,c1a[1]);
            c1a[2]=fma2(b23.x,p1r,c1a[2]); c1a[3]=fma2(b23.y,p1r,c1a[3]);
            c1a[4]=fma2(b45.x,p1r,c1a[4]); c1a[5]=fma2(b45.y,p1r,c1a[5]);
            c1a[6]=fma2(b67.x,p1r,c1a[6]); c1a[7]=fma2(b67.y,p1r,c1a[7]);
        }
        float ca0[16], ca1[16];
#pragma unroll
        for (int h = 0; h < 8; h++) {
            upk2(ca0[2*h], ca0[2*h+1], c0a[h]);
            upk2(ca1[2*h], ca1[2*h+1], c1a[h]);
        }
        float full0[15], full1[15];
        codon_full(nb + tid, full0);
        codon_full(nb + tid + 128, full1);
        const int gl0 = p0 + tid;
        const int gl1 = gl0 + 128;
        const float* hp0 = nullptr;
        const float* hp1 = nullptr;
        if (gl0 == 0)              hp0 = eh + b * 30;
        else if (gl0 == L_SEQ - 1) hp0 = eh + b * 30 + 15;
        if (gl1 == 0)              hp1 = eh + b * 30;
        else if (gl1 == L_SEQ - 1) hp1 = eh + b * 30 + 15;
#pragma unroll
        for (int q = 0; q < 15; q++) {
            float o0 = ca0[q] * full0[q];
            float o1 = ca1[q] * full1[q];
            if (hp0) o0 *= hp0[q];
            if (hp1) o1 *= hp1[q];
            row0[q] = o0;       // stage (ch slots 0..14 dead; [15] keeps dim0 x)
            row1[q] = o1;
        }
    }

    // ====== phase B: MVN exponents ======
    ull a0[16], a1[16];
#pragma unroll
    for (int q = 0; q < 16; q++) {
        float Kq = sm[K_OFF + q];
        ull init = pk2(Kq, 0.f);
        a0[q] = init; a1[q] = init;
    }

#define PROC_DIM(d, xA, xB)                                            \
    {                                                                  \
        ull xa = pk2((xA) * (xA), (xA));                               \
        ull xb = pk2((xB) * (xB), (xB));                               \
        const ulonglong2* cdim =                                       \
            (const ulonglong2*)(sm + AB_OFF + (d) * 32);               \
        _Pragma("unroll")                                              \
        for (int h = 0; h < 8; h++) {                                  \
            ulonglong2 cv = cdim[h];                                   \
            a0[2*h]   = fma2(cv.x, xa, a0[2*h]);                       \
            a0[2*h+1] = fma2(cv.y, xa, a0[2*h+1]);                     \
            a1[2*h]   = fma2(cv.x, xb, a1[2*h]);                       \
            a1[2*h+1] = fma2(cv.y, xb, a1[2*h+1]);                     \
        }                                                              \
    }

    PROC_DIM(0, row0[15], row1[15]);      // dim 0 = channel 15 (in C0)

    asm volatile("cp.async.wait_group 0;");  // E1 ready
    __syncthreads();

    const float* e0 = sm + E_OFF + tid * ES;
    const float* e1 = e0 + 128 * ES;
    // chunk 1: dims 1..32 (channels 16..47)
#pragma unroll 2
    for (int j = 0; j < 8; j++) {
        float4 v0 = *(const float4*)(e0 + 4 * j);
        float4 v1 = *(const float4*)(e1 + 4 * j);
        int d = 1 + 4 * j;
        PROC_DIM(d,     v0.x, v1.x);
        PROC_DIM(d + 1, v0.y, v1.y);
        PROC_DIM(d + 2, v0.z, v1.z);
        PROC_DIM(d + 3, v0.w, v1.w);
    }
    __syncthreads();   // everyone done with E1
    // reload E with channels 48..79
#pragma unroll 2
    for (int i = tid; i < NPOS * 8; i += THREADS) {
        int pos = i >> 3, j = i & 7;
        cp_async16(ebase + (pos * ES + j * 4) * 4, gbase + pos * CH + 48 + j * 4);
    }
    asm volatile("cp.async.commit_group;");
    asm volatile("cp.async.wait_group 0;");
    __syncthreads();
    // chunk 2: dims 33..63 (channels 48..78)
#pragma unroll 2
    for (int j = 0; j < 7; j++) {
        float4 v0 = *(const float4*)(e0 + 4 * j);
        float4 v1 = *(const float4*)(e1 + 4 * j);
        int d = 33 + 4 * j;
        PROC_DIM(d,     v0.x, v1.x);
        PROC_DIM(d + 1, v0.y, v1.y);
        PROC_DIM(d + 2, v0.z, v1.z);
        PROC_DIM(d + 3, v0.w, v1.w);
    }
    {
        float4 v0 = *(const float4*)(e0 + 28);   // ch 76..78 -> dims 61..63
        float4 v1 = *(const float4*)(e1 + 28);
        PROC_DIM(61, v0.x, v1.x);
        PROC_DIM(62, v0.y, v1.y);
        PROC_DIM(63, v0.z, v1.z);
    }

    // final: multiply staged values by exp2(exponent), in place
#pragma unroll
    for (int q = 0; q < 15; q++) {
        float lo, hi;
        upk2(lo, hi, a0[q]); row0[q] *= exp2f(lo + hi);
        upk2(lo, hi, a1[q]); row1[q] *= exp2f(lo + hi);
    }
    __syncthreads();

    // coalesced flush
    float* og = out + (size_t)(b * L_SEQ + p0) * 15;
#pragma unroll 6
    for (int i = tid; i < NPOS * 15; i += THREADS) {
        int pos = i / 15;
        int q   = i - pos * 15;
        og[i] = sm[C0_OFF + pos * C0S + q];
    }
}

extern "C" void kernel_launch(void* const* d_in, const int* in_sizes, int n_in,
                              void* d_out, int out_size) {
    const float *inp = nullptr, *eh = nullptr, *ek = nullptr, *eek = nullptr;
    for (int i = 0; i < n_in; i++) {
        switch (in_sizes[i]) {
            case 11010048: inp = (const float*)d_in[i]; break; // inputs
            case 480:      eh  = (const float*)d_in[i]; break; // end_hints
            case 225:      ek  = (const float*)d_in[i]; break; // emission_kernel
            case 1920:     eek = (const float*)d_in[i]; break; // embedding_emission_kernel
        }
    }
    float* out = (float*)d_out;

    cudaFuncSetAttribute(emit_kernel, cudaFuncAttributeMaxDynamicSharedMemorySize,
                         SMEM_BYTES);

    emit_kernel<<<(B_SEQ * L_SEQ) / NPOS, THREADS, SMEM_BYTES>>>(inp, eh, ek, eek, out);
}

// round 7
// speedup vs baseline: 1.1059x; 1.1059x over previous
#include <cuda_runtime.h>
#include <stdint.h>
#include <math.h>

#define NPOS 256          // positions per block
#define THREADS 128       // 2 positions per thread
#define CH 84
#define L_SEQ 8192
#define B_SEQ 16

// static smem layout (float offsets)
#define AB_OFF 0          // 64 dims * 16 * 2  = 2048 (states 0..14 used)
#define SB_OFF 2048       // class emit [s][q] = 256
#define K_OFF  2304       // 16
#define SCR_OFF 2320      // 240 prep scratch
#define NB_OFF 2560       // 260 float4 nuc halo = 1040
#define OUT_OFF 3600      // 256 * 17 output staging = 4352
#define SMEM_FLOATS 7952  // 31808 bytes -> 4 blocks/SM (reg-limited)

typedef unsigned long long ull;

__device__ __forceinline__ ull fma2(ull a, ull b, ull c) {
    ull d;
    asm("fma.rn.f32x2 %0, %1, %2, %3;" : "=l"(d) : "l"(a), "l"(b), "l"(c));
    return d;
}
__device__ __forceinline__ ull pk2(float lo, float hi) {
    ull d;
    asm("mov.b64 %0, {%1, %2};" : "=l"(d) : "f"(lo), "f"(hi));
    return d;
}
__device__ __forceinline__ void upk2(float& lo, float& hi, ull v) {
    asm("mov.b64 {%0, %1}, %2;" : "=f"(lo), "=f"(hi) : "l"(v));
}

__device__ __forceinline__ void codon_full(const float4* nbp, float* fullv) {
    float4 m2 = nbp[0], m1 = nbp[1], c0 = nbp[2], q1 = nbp[3], q2 = nbp[4];
    float S_c0 = c0.x + c0.y + c0.z + c0.w;
    float S_q1 = q1.x + q1.y + q1.z + q1.w;
    float S_q2 = q2.x + q2.y + q2.z + q2.w;
    float S_m1 = m1.x + m1.y + m1.z + m1.w;
    float S_m2 = m2.x + m2.y + m2.z + m2.w;
    float L_any   = S_c0 * S_q1 * S_q2 * (1.f / 64.f);
    float L_start = c0.x * q1.w * q2.z;           // ATG
    float L_ib    = 0.25f * S_c0 * q1.z * q2.w;   // NGT
    float Pall = S_m2 * S_m1 * S_c0;
    float tAA = m1.x * c0.x, tAG = m1.x * c0.z, tGA = m1.z * c0.x;
    float R_ns   = (Pall - m2.w * (tAA + tAG + tGA)) * (1.f / 61.f);
    float R_any  = Pall * (1.f / 64.f);
    float R_iep  = m2.x * m1.z * 0.25f * S_c0;    // AGN
    float R_stop = m2.w * (0.34f * tAA + 0.33f * tAG + 0.33f * tGA);
    fullv[0] = 1.f; fullv[1] = 1.f; fullv[2] = 1.f;
    fullv[3] = 1.f; fullv[4] = 1.f; fullv[5] = 1.f;
    fullv[6]  = L_any * R_ns;
    fullv[7]  = L_start * R_any;
    fullv[8]  = L_ib * R_any;
    fullv[9]  = L_ib * R_ns;
    fullv[10] = L_ib * R_any;
    fullv[11] = L_any * R_iep;
    fullv[12] = L_any * R_iep;
    fullv[13] = L_any * R_iep;
    fullv[14] = L_any * R_stop;
}

__global__ void __launch_bounds__(THREADS, 4)
emit_kernel(const float* __restrict__ inputs,
            const float* __restrict__ eh,
            const float* __restrict__ ek,
            const float* __restrict__ eek,
            float* __restrict__ out) {
    __shared__ float sh[SMEM_FLOATS];
    const int tid = threadIdx.x;
    const int b  = blockIdx.x >> 5;
    const int p0 = (blockIdx.x & 31) << 8;
    const float* gbase = inputs + (size_t)(b * L_SEQ + p0) * CH;

    // ---------------- inline prep ----------------
    const float kscale = (float)(1.4426950408889634 / 100.0); // log2(e)/TEMP
    const float basec  = (float)log(expm1(sqrt(0.05)));
    const float cconst = (float)(0.5 * 64.0 * log(2.0 * M_PI));

    if (tid < 15) {               // softmax rows -> SB[s][q] = B[q][s]
        int q = tid;
        float m = -1e30f;
        for (int s = 0; s < 15; s++) m = fmaxf(m, ek[q * 15 + s]);
        float e[15]; float sum = 0.f;
        for (int s = 0; s < 15; s++) { e[s] = expf(ek[q * 15 + s] - m); sum += e[s]; }
        float inv = 1.f / sum;
        for (int s = 0; s < 15; s++) sh[SB_OFF + s * 16 + q] = e[s] * inv;
    }
    if (tid == 15) {
        for (int s = 0; s < 16; s++) sh[SB_OFF + s * 16 + 15] = 0.f;
    }
    if (tid < 120) {              // MVN coefficients, thread = (state, dim-octet)
        int s = tid >> 3, g = tid & 7;
        float Cp = 0.f, ldp = 0.f;
        for (int k = 0; k < 8; k++) {
            int d = g * 8 + k;
            float mu = eek[s * 128 + d];
            float v  = eek[s * 128 + 64 + d] + basec;
            float sp = (v > 20.f) ? v : log1pf(expf(v));
            float is2 = 1.f / (sp * sp);
            sh[AB_OFF + d * 32 + s * 2 + 0] = -0.5f * is2 * kscale;
            sh[AB_OFF + d * 32 + s * 2 + 1] = mu * is2 * kscale;
            Cp  = fmaf(mu * mu, is2, Cp);
            ldp += logf(sp);
        }
        sh[SCR_OFF + tid * 2 + 0] = Cp;
        sh[SCR_OFF + tid * 2 + 1] = ldp;
    }

    // ---------------- nuc halo buffer (direct from global) ----------------
    float4* nb = (float4*)(sh + NB_OFF);
#pragma unroll 2
    for (int i = tid; i < NPOS + 4; i += THREADS) {
        int gl = p0 + i - 2;
        float4 nv;
        if (gl >= 0 && gl < L_SEQ) {
            const float* nr = inputs + (size_t)(b * L_SEQ + gl) * CH;
            float n0 = nr[79];
            float4 f = *(const float4*)(nr + 80);   // ch 80..83
            nv = make_float4(fmaf(0.25f, f.w, n0),  fmaf(0.25f, f.w, f.x),
                             fmaf(0.25f, f.w, f.y), fmaf(0.25f, f.w, f.z));
        } else {
            nv = make_float4(0.25f, 0.25f, 0.25f, 0.25f);
        }
        nb[i] = nv;
    }
    __syncthreads();
    if (tid < 15) {
        float C = 0.f, ld = 0.f;
        for (int g = 0; g < 8; g++) {
            C  += sh[SCR_OFF + (tid * 8 + g) * 2 + 0];
            ld += sh[SCR_OFF + (tid * 8 + g) * 2 + 1];
        }
        sh[K_OFF + tid] = (-0.5f * C - ld - cconst) * kscale;
    }
    __syncthreads();

    const float* row0 = gbase + tid * CH;          // global rows (direct LDG)
    const float* row1 = row0 + 128 * CH;
    float x15_0, x15_1;                            // emb dim0 (channel 15)

    // ====== phase A: class matvec + codon + hints -> staged to OUT rows ======
    {
        float cls0[16], cls1[16];
#pragma unroll
        for (int j = 0; j < 4; j++) {
            *(float4*)(cls0 + 4 * j) = *(const float4*)(row0 + 4 * j);
            *(float4*)(cls1 + 4 * j) = *(const float4*)(row1 + 4 * j);
        }
        x15_0 = cls0[15]; x15_1 = cls1[15];
        ull c0a[8], c1a[8];
#pragma unroll
        for (int h = 0; h < 8; h++) { c0a[h] = 0; c1a[h] = 0; }
#pragma unroll 3
        for (int s = 0; s < 15; s++) {
            const ulonglong2* br = (const ulonglong2*)(sh + SB_OFF + s * 16);
            ulonglong2 b01 = br[0], b23 = br[1], b45 = br[2], b67 = br[3];
            ull p0r = pk2(cls0[s], cls0[s]);
            ull p1r = pk2(cls1[s], cls1[s]);
            c0a[0]=fma2(b01.x,p0r,c0a[0]); c0a[1]=fma2(b01.y,p0r,c0a[1]);
            c0a[2]=fma2(b23.x,p0r,c0a[2]); c0a[3]=fma2(b23.y,p0r,c0a[3]);
            c0a[4]=fma2(b45.x,p0r,c0a[4]); c0a[5]=fma2(b45.y,p0r,c0a[5]);
            c0a[6]=fma2(b67.x,p0r,c0a[6]); c0a[7]=fma2(b67.y,p0r,c0a[7]);
            c1a[0]=fma2(b01.x,p1r,c1a[0]); c1a[1]=fma2(b01.y,p1r,c1a[1]);
            c1a[2]=fma2(b23.x,p1r,c1a[2]); c1a[3]=fma2(b23.y,p1r,c1a[3]);
            c1a[4]=fma2(b45.x,p1r,c1a[4]); c1a[5]=fma2(b45.y,p1r,c1a[5]);
            c1a[6]=fma2(b67.x,p1r,c1a[6]); c1a[7]=fma2(b67.y,p1r,c1a[7]);
        }
        float ca0[16], ca1[16];
#pragma unroll
        for (int h = 0; h < 8; h++) {
            upk2(ca0[2*h], ca0[2*h+1], c0a[h]);
            upk2(ca1[2*h], ca1[2*h+1], c1a[h]);
        }
        float full0[15], full1[15];
        codon_full(nb + tid, full0);
        codon_full(nb + tid + 128, full1);
        const int gl0 = p0 + tid;
        const int gl1 = gl0 + 128;
        const float* hp0 = nullptr;
        const float* hp1 = nullptr;
        if (gl0 == 0)              hp0 = eh + b * 30;
        else if (gl0 == L_SEQ - 1) hp0 = eh + b * 30 + 15;
        if (gl1 == 0)              hp1 = eh + b * 30;
        else if (gl1 == L_SEQ - 1) hp1 = eh + b * 30 + 15;
        float* wr0 = sh + OUT_OFF + tid * 17;
        float* wr1 = wr0 + 128 * 17;
#pragma unroll
        for (int q = 0; q < 15; q++) {
            float o0 = ca0[q] * full0[q];
            float o1 = ca1[q] * full1[q];
            if (hp0) o0 *= hp0[q];
            if (hp1) o1 *= hp1[q];
            wr0[q] = o0;
            wr1[q] = o1;
        }
    }

    // ====== phase B: MVN exponents (15 states, 2 positions) ======
    ull a0[15], a1[15];
#pragma unroll
    for (int q = 0; q < 15; q++) {
        float Kq = sh[K_OFF + q];
        ull init = pk2(Kq, 0.f);
        a0[q] = init; a1[q] = init;
    }

#define PROC_DIM(d, xA, xB)                                            \
    {                                                                  \
        ull xa = pk2((xA) * (xA), (xA));                               \
        ull xb = pk2((xB) * (xB), (xB));                               \
        const ulonglong2* cdim =                                       \
            (const ulonglong2*)(sh + AB_OFF + (d) * 32);               \
        _Pragma("unroll")                                              \
        for (int h = 0; h < 7; h++) {                                  \
            ulonglong2 cv = cdim[h];                                   \
            a0[2*h]   = fma2(cv.x, xa, a0[2*h]);                       \
            a0[2*h+1] = fma2(cv.y, xa, a0[2*h+1]);                     \
            a1[2*h]   = fma2(cv.x, xb, a1[2*h]);                       \
            a1[2*h+1] = fma2(cv.y, xb, a1[2*h+1]);                     \
        }                                                              \
        ull cv14 = *(const ull*)(sh + AB_OFF + (d) * 32 + 28);         \
        a0[14] = fma2(cv14, xa, a0[14]);                               \
        a1[14] = fma2(cv14, xb, a1[14]);                               \
    }

    PROC_DIM(0, x15_0, x15_1);          // emb dim 0 = channel 15

    const float4* g0 = (const float4*)(row0 + 16);   // channels 16..79
    const float4* g1 = (const float4*)(row1 + 16);
    float4 v0 = g0[0], v1 = g1[0];
#pragma unroll
    for (int j = 0; j < 15; j++) {      // dims 1..60
        float4 n0, n1;
        if (j < 14) { n0 = g0[j + 1]; n1 = g1[j + 1]; }
        int d = 4 * j + 1;
        PROC_DIM(d,     v0.x, v1.x);
        PROC_DIM(d + 1, v0.y, v1.y);
        PROC_DIM(d + 2, v0.z, v1.z);
        PROC_DIM(d + 3, v0.w, v1.w);
        if (j < 14) { v0 = n0; v1 = n1; }
    }
    {
        float4 t0 = g0[15], t1 = g1[15];  // channels 76..79 -> dims 61..63
        PROC_DIM(61, t0.x, t1.x);
        PROC_DIM(62, t0.y, t1.y);
        PROC_DIM(63, t0.z, t1.z);
    }

    // finalize: multiply staged (class*codon*hint) by exp2(exponent)
    {
        float* wr0 = sh + OUT_OFF + tid * 17;
        float* wr1 = wr0 + 128 * 17;
#pragma unroll
        for (int q = 0; q < 15; q++) {
            float lo, hi;
            upk2(lo, hi, a0[q]); wr0[q] *= exp2f(lo + hi);
            upk2(lo, hi, a1[q]); wr1[q] *= exp2f(lo + hi);
        }
    }
    __syncthreads();

    // coalesced flush (incremental pos/q to avoid divisions)
    float* og = out + (size_t)(b * L_SEQ + p0) * 15;
    int pos = tid / 15;
    int q   = tid - pos * 15;
#pragma unroll 6
    for (int i = tid; i < NPOS * 15; i += THREADS) {
        og[i] = sh[OUT_OFF + pos * 17 + q];
        pos += 8; q += 8;
        if (q >= 15) { q -= 15; pos += 1; }
    }
}

extern "C" void kernel_launch(void* const* d_in, const int* in_sizes, int n_in,
                              void* d_out, int out_size) {
    const float *inp = nullptr, *eh = nullptr, *ek = nullptr, *eek = nullptr;
    for (int i = 0; i < n_in; i++) {
        switch (in_sizes[i]) {
            case 11010048: inp = (const float*)d_in[i]; break; // inputs
            case 480:      eh  = (const float*)d_in[i]; break; // end_hints
            case 225:      ek  = (const float*)d_in[i]; break; // emission_kernel
            case 1920:     eek = (const float*)d_in[i]; break; // embedding_emission_kernel
        }
    }
    float* out = (float*)d_out;

    emit_kernel<<<(B_SEQ * L_SEQ) / NPOS, THREADS>>>(inp, eh, ek, eek, out);
}

// round 8
// speedup vs baseline: 1.1091x; 1.0029x over previous
#include <cuda_runtime.h>
#include <stdint.h>
#include <math.h>

#define NPOS 256          // positions per block
#define THREADS 128       // 2 positions per thread
#define CH 84
#define L_SEQ 8192
#define B_SEQ 16

// static smem layout (float offsets)
#define AB_OFF 0          // 64 dims * 16 * 2  = 2048 (states 0..14 used)
#define SB_OFF 2048       // class emit [s][q] = 256
#define K_OFF  2304       // 16
#define SCR_OFF 2320      // 240 prep scratch
#define NB_OFF 2560       // 260 float4 nuc halo = 1040
#define OUT_OFF 3600      // 256 * 17 output staging = 4352
#define SMEM_FLOATS 7952  // 31808 bytes -> 4 blocks/SM

__device__ __forceinline__ float ex2(float x) {
    float r;
    asm("ex2.approx.ftz.f32 %0, %1;" : "=f"(r) : "f"(x));
    return r;
}

__device__ __forceinline__ void codon_full(const float4* nbp, float* fullv) {
    float4 m2 = nbp[0], m1 = nbp[1], c0 = nbp[2], q1 = nbp[3], q2 = nbp[4];
    float S_c0 = c0.x + c0.y + c0.z + c0.w;
    float S_q1 = q1.x + q1.y + q1.z + q1.w;
    float S_q2 = q2.x + q2.y + q2.z + q2.w;
    float S_m1 = m1.x + m1.y + m1.z + m1.w;
    float S_m2 = m2.x + m2.y + m2.z + m2.w;
    float L_any   = S_c0 * S_q1 * S_q2 * (1.f / 64.f);
    float L_start = c0.x * q1.w * q2.z;           // ATG
    float L_ib    = 0.25f * S_c0 * q1.z * q2.w;   // NGT
    float Pall = S_m2 * S_m1 * S_c0;
    float tAA = m1.x * c0.x, tAG = m1.x * c0.z, tGA = m1.z * c0.x;
    float R_ns   = (Pall - m2.w * (tAA + tAG + tGA)) * (1.f / 61.f);
    float R_any  = Pall * (1.f / 64.f);
    float R_iep  = m2.x * m1.z * 0.25f * S_c0;    // AGN
    float R_stop = m2.w * (0.34f * tAA + 0.33f * tAG + 0.33f * tGA);
    fullv[0] = 1.f; fullv[1] = 1.f; fullv[2] = 1.f;
    fullv[3] = 1.f; fullv[4] = 1.f; fullv[5] = 1.f;
    fullv[6]  = L_any * R_ns;
    fullv[7]  = L_start * R_any;
    fullv[8]  = L_ib * R_any;
    fullv[9]  = L_ib * R_ns;
    fullv[10] = L_ib * R_any;
    fullv[11] = L_any * R_iep;
    fullv[12] = L_any * R_iep;
    fullv[13] = L_any * R_iep;
    fullv[14] = L_any * R_stop;
}

__global__ void __launch_bounds__(THREADS, 4)
emit_kernel(const float* __restrict__ inputs,
            const float* __restrict__ eh,
            const float* __restrict__ ek,
            const float* __restrict__ eek,
            float* __restrict__ out) {
    __shared__ float sh[SMEM_FLOATS];
    const int tid = threadIdx.x;
    const int b  = blockIdx.x >> 5;
    const int p0 = (blockIdx.x & 31) << 8;
    const float* gbase = inputs + (size_t)(b * L_SEQ + p0) * CH;

    // ---------------- inline prep ----------------
    const float kscale = (float)(1.4426950408889634 / 100.0); // log2(e)/TEMP
    const float basec  = (float)log(expm1(sqrt(0.05)));
    const float cconst = (float)(0.5 * 64.0 * log(2.0 * M_PI));

    if (tid < 15) {               // softmax rows -> SB[s][q] = B[q][s]
        int q = tid;
        float m = -1e30f;
        for (int s = 0; s < 15; s++) m = fmaxf(m, ek[q * 15 + s]);
        float e[15]; float sum = 0.f;
        for (int s = 0; s < 15; s++) { e[s] = expf(ek[q * 15 + s] - m); sum += e[s]; }
        float inv = 1.f / sum;
        for (int s = 0; s < 15; s++) sh[SB_OFF + s * 16 + q] = e[s] * inv;
    }
    if (tid == 15) {
        for (int s = 0; s < 16; s++) sh[SB_OFF + s * 16 + 15] = 0.f;
    }
    if (tid < 120) {              // MVN coefficients, thread = (state, dim-octet)
        int s = tid >> 3, g = tid & 7;
        float Cp = 0.f, ldp = 0.f;
        for (int k = 0; k < 8; k++) {
            int d = g * 8 + k;
            float mu = eek[s * 128 + d];
            float v  = eek[s * 128 + 64 + d] + basec;
            float sp = (v > 20.f) ? v : log1pf(expf(v));
            float is2 = 1.f / (sp * sp);
            sh[AB_OFF + d * 32 + s * 2 + 0] = -0.5f * is2 * kscale;  // A'
            sh[AB_OFF + d * 32 + s * 2 + 1] = mu * is2 * kscale;     // B'
            Cp  = fmaf(mu * mu, is2, Cp);
            ldp += logf(sp);
        }
        sh[SCR_OFF + tid * 2 + 0] = Cp;
        sh[SCR_OFF + tid * 2 + 1] = ldp;
    }

    // ---------------- nuc halo buffer (direct from global) ----------------
    float4* nb = (float4*)(sh + NB_OFF);
#pragma unroll 2
    for (int i = tid; i < NPOS + 4; i += THREADS) {
        int gl = p0 + i - 2;
        float4 nv;
        if (gl >= 0 && gl < L_SEQ) {
            const float* nr = inputs + (size_t)(b * L_SEQ + gl) * CH;
            float n0 = nr[79];
            float4 f = *(const float4*)(nr + 80);   // ch 80..83
            nv = make_float4(fmaf(0.25f, f.w, n0),  fmaf(0.25f, f.w, f.x),
                             fmaf(0.25f, f.w, f.y), fmaf(0.25f, f.w, f.z));
        } else {
            nv = make_float4(0.25f, 0.25f, 0.25f, 0.25f);
        }
        nb[i] = nv;
    }
    __syncthreads();
    if (tid < 15) {
        float C = 0.f, ld = 0.f;
        for (int g = 0; g < 8; g++) {
            C  += sh[SCR_OFF + (tid * 8 + g) * 2 + 0];
            ld += sh[SCR_OFF + (tid * 8 + g) * 2 + 1];
        }
        sh[K_OFF + tid] = (-0.5f * C - ld - cconst) * kscale;
    }
    __syncthreads();

    const float* row0 = gbase + tid * CH;          // global rows (direct LDG)
    const float* row1 = row0 + 128 * CH;
    float x15_0, x15_1;                            // emb dim0 (channel 15)

    // ====== phase A: class matvec + codon + hints -> staged to OUT rows ======
    {
        float cls0[16], cls1[16];
#pragma unroll
        for (int j = 0; j < 4; j++) {
            *(float4*)(cls0 + 4 * j) = *(const float4*)(row0 + 4 * j);
            *(float4*)(cls1 + 4 * j) = *(const float4*)(row1 + 4 * j);
        }
        x15_0 = cls0[15]; x15_1 = cls1[15];
        float ca0[16], ca1[16];
#pragma unroll
        for (int q = 0; q < 16; q++) { ca0[q] = 0.f; ca1[q] = 0.f; }
#pragma unroll 3
        for (int s = 0; s < 15; s++) {
            const float4* br = (const float4*)(sh + SB_OFF + s * 16);
            float xs0 = cls0[s], xs1 = cls1[s];
#pragma unroll
            for (int h = 0; h < 4; h++) {
                float4 bv = br[h];
                ca0[4*h+0] = fmaf(bv.x, xs0, ca0[4*h+0]);
                ca0[4*h+1] = fmaf(bv.y, xs0, ca0[4*h+1]);
                ca0[4*h+2] = fmaf(bv.z, xs0, ca0[4*h+2]);
                ca0[4*h+3] = fmaf(bv.w, xs0, ca0[4*h+3]);
                ca1[4*h+0] = fmaf(bv.x, xs1, ca1[4*h+0]);
                ca1[4*h+1] = fmaf(bv.y, xs1, ca1[4*h+1]);
                ca1[4*h+2] = fmaf(bv.z, xs1, ca1[4*h+2]);
                ca1[4*h+3] = fmaf(bv.w, xs1, ca1[4*h+3]);
            }
        }
        float full0[15], full1[15];
        codon_full(nb + tid, full0);
        codon_full(nb + tid + 128, full1);
        const int gl0 = p0 + tid;
        const int gl1 = gl0 + 128;
        const float* hp0 = nullptr;
        const float* hp1 = nullptr;
        if (gl0 == 0)              hp0 = eh + b * 30;
        else if (gl0 == L_SEQ - 1) hp0 = eh + b * 30 + 15;
        if (gl1 == 0)              hp1 = eh + b * 30;
        else if (gl1 == L_SEQ - 1) hp1 = eh + b * 30 + 15;
        float* wr0 = sh + OUT_OFF + tid * 17;
        float* wr1 = wr0 + 128 * 17;
#pragma unroll
        for (int q = 0; q < 15; q++) {
            float o0 = ca0[q] * full0[q];
            float o1 = ca1[q] * full1[q];
            if (hp0) o0 *= hp0[q];
            if (hp1) o1 *= hp1[q];
            wr0[q] = o0;
            wr1[q] = o1;
        }
    }

    // ====== phase B: MVN exponents (15 states, 2 positions, scalar FFMA) ======
    float a0[15], a1[15];
#pragma unroll
    for (int q = 0; q < 15; q++) {
        float Kq = sh[K_OFF + q];
        a0[q] = Kq; a1[q] = Kq;
    }

#define PROC_DIM(d, xA, xB)                                              \
    {                                                                    \
        float xa2 = (xA) * (xA);                                         \
        float xb2 = (xB) * (xB);                                         \
        const float4* cf = (const float4*)(sh + AB_OFF + (d) * 32);      \
        _Pragma("unroll")                                                \
        for (int h = 0; h < 7; h++) {                                    \
            float4 c = cf[h];                                            \
            a0[2*h]   = fmaf(c.x, xa2, fmaf(c.y, (xA), a0[2*h]));        \
            a0[2*h+1] = fmaf(c.z, xa2, fmaf(c.w, (xA), a0[2*h+1]));      \
            a1[2*h]   = fmaf(c.x, xb2, fmaf(c.y, (xB), a1[2*h]));        \
            a1[2*h+1] = fmaf(c.z, xb2, fmaf(c.w, (xB), a1[2*h+1]));      \
        }                                                                \
        float2 c14 = *(const float2*)(sh + AB_OFF + (d) * 32 + 28);      \
        a0[14] = fmaf(c14.x, xa2, fmaf(c14.y, (xA), a0[14]));            \
        a1[14] = fmaf(c14.x, xb2, fmaf(c14.y, (xB), a1[14]));            \
    }

    PROC_DIM(0, x15_0, x15_1);          // emb dim 0 = channel 15

    const float4* g0 = (const float4*)(row0 + 16);   // channels 16..79
    const float4* g1 = (const float4*)(row1 + 16);
    float4 v0 = g0[0], v1 = g1[0];
#pragma unroll 3
    for (int j = 0; j < 15; j++) {      // dims 1..60
        float4 n0, n1;
        if (j < 14) { n0 = g0[j + 1]; n1 = g1[j + 1]; }
        int d = 4 * j + 1;
        PROC_DIM(d,     v0.x, v1.x);
        PROC_DIM(d + 1, v0.y, v1.y);
        PROC_DIM(d + 2, v0.z, v1.z);
        PROC_DIM(d + 3, v0.w, v1.w);
        if (j < 14) { v0 = n0; v1 = n1; }
    }
    {
        float4 t0 = g0[15], t1 = g1[15];  // channels 76..79 -> dims 61..63
        PROC_DIM(61, t0.x, t1.x);
        PROC_DIM(62, t0.y, t1.y);
        PROC_DIM(63, t0.z, t1.z);
    }

    // finalize: multiply staged (class*codon*hint) by exp2(exponent)
    {
        float* wr0 = sh + OUT_OFF + tid * 17;
        float* wr1 = wr0 + 128 * 17;
#pragma unroll
        for (int q = 0; q < 15; q++) {
            wr0[q] *= ex2(a0[q]);
            wr1[q] *= ex2(a1[q]);
        }
    }
    __syncthreads();

    // coalesced flush (incremental pos/q to avoid divisions)
    float* og = out + (size_t)(b * L_SEQ + p0) * 15;
    int pos = tid / 15;
    int q   = tid - pos * 15;
#pragma unroll 6
    for (int i = tid; i < NPOS * 15; i += THREADS) {
        og[i] = sh[OUT_OFF + pos * 17 + q];
        pos += 8; q += 8;
        if (q >= 15) { q -= 15; pos += 1; }
    }
}

extern "C" void kernel_launch(void* const* d_in, const int* in_sizes, int n_in,
                              void* d_out, int out_size) {
    const float *inp = nullptr, *eh = nullptr, *ek = nullptr, *eek = nullptr;
    for (int i = 0; i < n_in; i++) {
        switch (in_sizes[i]) {
            case 11010048: inp = (const float*)d_in[i]; break; // inputs
            case 480:      eh  = (const float*)d_in[i]; break; // end_hints
            case 225:      ek  = (const float*)d_in[i]; break; // emission_kernel
            case 1920:     eek = (const float*)d_in[i]; break; // embedding_emission_kernel
        }
    }
    float* out = (float*)d_out;

    emit_kernel<<<(B_SEQ * L_SEQ) / NPOS, THREADS>>>(inp, eh, ek, eek, out);
}